// round 1
// baseline (speedup 1.0000x reference)
#include <cuda_runtime.h>

// ---------------------------------------------------------------------------
// CrossBundleAttention — fp32 baseline
// B=64, M=2048, D_LLM=4096, bundles: (d=256,nh=4,s=4) (512,8,8) (1024,16,4)
// head_dim = 64 for every bundle. Output (64, 16, 4096) fp32.
// ---------------------------------------------------------------------------

#define BATCH 64
#define MEM   2048
#define DLLM  4096
#define BM 64
#define BN 64
#define BK 16
#define PAD 68   // 68*4 = 272 bytes, multiple of 16 -> float4-aligned rows

// ------------------------- scratch (device globals) ------------------------
__device__ float g_qb[BATCH * 1024];          // bundle query  (B, d)
__device__ float g_qp[BATCH * 1024];          // in-proj'd scaled query (B, d)
__device__ float g_k [MEM * 1024];            // K projection  (M, d)
__device__ float g_v [MEM * 1024];            // V projection  (M, d)
__device__ float g_o [BATCH * 1024];          // attention out (B, d)
__device__ float g_o2[BATCH * 1024];          // out-proj      (B, d)
__device__ float g_part[8 * BATCH * 1024];    // split-K partials
__device__ float g_prefix[BATCH * 16 * DLLM]; // pre-LN prefix

// ---------------------------------------------------------------------------
// GEMM-NT (full K):  C(M,N) = alpha * (A(M,K) @ W(N,K)^T + bias(N))
// row-major everywhere; M,N multiples of 64, K multiple of 16.
// ---------------------------------------------------------------------------
__global__ void __launch_bounds__(256) gemm_nt_full(
    const float* __restrict__ A, const float* __restrict__ W,
    const float* __restrict__ bias, float* __restrict__ C,
    int N, int K, float alpha)
{
    __shared__ float As[BK][PAD];
    __shared__ float Ws[BK][PAD];
    const int tid = threadIdx.x;
    const int tx = tid & 15, ty = tid >> 4;
    const int mBase = blockIdx.y * BM, nBase = blockIdx.x * BN;
    const int lr = tid >> 2;            // 0..63
    const int lc = (tid & 3) << 2;      // 0,4,8,12
    const float* Ap = A + (size_t)(mBase + lr) * K + lc;
    const float* Wp = W + (size_t)(nBase + lr) * K + lc;
    float acc[4][4] = {};
    for (int k0 = 0; k0 < K; k0 += BK) {
        float4 a4 = *(const float4*)(Ap + k0);
        float4 w4 = *(const float4*)(Wp + k0);
        As[lc + 0][lr] = a4.x; As[lc + 1][lr] = a4.y;
        As[lc + 2][lr] = a4.z; As[lc + 3][lr] = a4.w;
        Ws[lc + 0][lr] = w4.x; Ws[lc + 1][lr] = w4.y;
        Ws[lc + 2][lr] = w4.z; Ws[lc + 3][lr] = w4.w;
        __syncthreads();
#pragma unroll
        for (int kk = 0; kk < BK; kk++) {
            float4 av = *(const float4*)&As[kk][ty << 2];
            float4 wv = *(const float4*)&Ws[kk][tx << 2];
            float am[4] = {av.x, av.y, av.z, av.w};
            float wm[4] = {wv.x, wv.y, wv.z, wv.w};
#pragma unroll
            for (int i = 0; i < 4; i++)
#pragma unroll
                for (int j = 0; j < 4; j++)
                    acc[i][j] += am[i] * wm[j];
        }
        __syncthreads();
    }
#pragma unroll
    for (int i = 0; i < 4; i++) {
        const int m = mBase + (ty << 2) + i;
#pragma unroll
        for (int j = 0; j < 4; j++) {
            const int n = nBase + (tx << 2) + j;
            C[(size_t)m * N + n] = alpha * (acc[i][j] + bias[n]);
        }
    }
}

// ---------------------------------------------------------------------------
// GEMM-NT split-K (M fixed = 64): partials into Cpart[z][64][N], KS = 8.
// ---------------------------------------------------------------------------
__global__ void __launch_bounds__(256) gemm_nt_splitk(
    const float* __restrict__ A, const float* __restrict__ W,
    float* __restrict__ Cpart, int N, int K)
{
    __shared__ float As[BK][PAD];
    __shared__ float Ws[BK][PAD];
    const int tid = threadIdx.x;
    const int tx = tid & 15, ty = tid >> 4;
    const int nBase = blockIdx.x * BN;
    const int z = blockIdx.z;
    const int kc = K >> 3;              // K / 8
    const int lr = tid >> 2;
    const int lc = (tid & 3) << 2;
    const float* Ap = A + (size_t)lr * K + lc;
    const float* Wp = W + (size_t)(nBase + lr) * K + lc;
    float acc[4][4] = {};
    const int kEnd = z * kc + kc;
    for (int k0 = z * kc; k0 < kEnd; k0 += BK) {
        float4 a4 = *(const float4*)(Ap + k0);
        float4 w4 = *(const float4*)(Wp + k0);
        As[lc + 0][lr] = a4.x; As[lc + 1][lr] = a4.y;
        As[lc + 2][lr] = a4.z; As[lc + 3][lr] = a4.w;
        Ws[lc + 0][lr] = w4.x; Ws[lc + 1][lr] = w4.y;
        Ws[lc + 2][lr] = w4.z; Ws[lc + 3][lr] = w4.w;
        __syncthreads();
#pragma unroll
        for (int kk = 0; kk < BK; kk++) {
            float4 av = *(const float4*)&As[kk][ty << 2];
            float4 wv = *(const float4*)&Ws[kk][tx << 2];
            float am[4] = {av.x, av.y, av.z, av.w};
            float wm[4] = {wv.x, wv.y, wv.z, wv.w};
#pragma unroll
            for (int i = 0; i < 4; i++)
#pragma unroll
                for (int j = 0; j < 4; j++)
                    acc[i][j] += am[i] * wm[j];
        }
        __syncthreads();
    }
    float* Cp = Cpart + (size_t)z * BATCH * N;
#pragma unroll
    for (int i = 0; i < 4; i++) {
        const int m = (ty << 2) + i;
#pragma unroll
        for (int j = 0; j < 4; j++) {
            const int n = nBase + (tx << 2) + j;
            Cp[(size_t)m * N + n] = acc[i][j];
        }
    }
}

// sum 8 partials + bias, scale by alpha
__global__ void reduce8(const float* __restrict__ part, const float* __restrict__ bias,
                        float* __restrict__ C, int MN, int N, float alpha)
{
    const int i = blockIdx.x * 256 + threadIdx.x;
    if (i >= MN) return;
    float s = bias[i % N];
#pragma unroll
    for (int z = 0; z < 8; z++) s += part[(size_t)z * MN + i];
    C[i] = alpha * s;
}

// ---------------------------------------------------------------------------
// Fused single-token attention: one block per (head, batch).
// qp already scaled by 1/sqrt(64). K/V: (M, d) row-major, head h = cols h*64..
// ---------------------------------------------------------------------------
__global__ void __launch_bounds__(256) attn_kernel(
    const float* __restrict__ qp, const float* __restrict__ Kp,
    const float* __restrict__ Vp, const unsigned char* __restrict__ mask,
    float* __restrict__ o, int d)
{
    __shared__ float sc[MEM];
    __shared__ float qs[64];
    __shared__ float red[8];
    __shared__ float outw[8][64];
    __shared__ float s_mx, s_sum;
    const int h = blockIdx.x, b = blockIdx.y;
    const int base = h << 6;
    const int tid = threadIdx.x, lane = tid & 31, warp = tid >> 5;

    if (tid < 64) qs[tid] = qp[(size_t)b * d + base + tid];
    __syncthreads();

    const unsigned char* mrow = mask + (size_t)b * MEM;
    for (int m = warp; m < MEM; m += 8) {
        const float* kr = Kp + (size_t)m * d + base;
        float p = qs[lane] * kr[lane] + qs[lane + 32] * kr[lane + 32];
#pragma unroll
        for (int off = 16; off; off >>= 1) p += __shfl_xor_sync(0xffffffffu, p, off);
        if (lane == 0) sc[m] = mrow[m] ? -1e9f : p;
    }
    __syncthreads();

    float mx = -1e30f;
    for (int m = tid; m < MEM; m += 256) mx = fmaxf(mx, sc[m]);
#pragma unroll
    for (int off = 16; off; off >>= 1) mx = fmaxf(mx, __shfl_xor_sync(0xffffffffu, mx, off));
    if (lane == 0) red[warp] = mx;
    __syncthreads();
    if (tid == 0) {
        float m2 = red[0];
#pragma unroll
        for (int w = 1; w < 8; w++) m2 = fmaxf(m2, red[w]);
        s_mx = m2;
    }
    __syncthreads();
    mx = s_mx;

    float sum = 0.f;
    for (int m = tid; m < MEM; m += 256) {
        float e = __expf(sc[m] - mx);
        sc[m] = e;
        sum += e;
    }
#pragma unroll
    for (int off = 16; off; off >>= 1) sum += __shfl_xor_sync(0xffffffffu, sum, off);
    __syncthreads();
    if (lane == 0) red[warp] = sum;
    __syncthreads();
    if (tid == 0) {
        float s2 = 0.f;
#pragma unroll
        for (int w = 0; w < 8; w++) s2 += red[w];
        s_sum = s2;
    }

    // weighted V accumulation: warp w owns m in [w*256, w*256+256)
    float a0 = 0.f, a1 = 0.f;
    const int m0 = warp << 8;
    for (int m = m0; m < m0 + 256; m++) {
        const float p = sc[m];
        const float* vr = Vp + (size_t)m * d + base;
        a0 += p * vr[lane];
        a1 += p * vr[lane + 32];
    }
    outw[warp][lane] = a0;
    outw[warp][lane + 32] = a1;
    __syncthreads();
    if (tid < 64) {
        float s = 0.f;
#pragma unroll
        for (int w = 0; w < 8; w++) s += outw[w][tid];
        o[(size_t)b * d + base + tid] = s * (1.0f / s_sum);
    }
}

// ---------------------------------------------------------------------------
// Lift GEMM-NN: out[b, slotBase+s, n] = sum_k o2[b,k]*Wlift[s,k,n] + blift[s,n]
// grid = (4096/64, 1, slots); M = 64.
// ---------------------------------------------------------------------------
__global__ void __launch_bounds__(256) gemm_nn_lift(
    const float* __restrict__ A, const float* __restrict__ Bw,
    const float* __restrict__ bias, float* __restrict__ outp,
    int K, int slotBase)
{
    __shared__ float As[BK][PAD];
    __shared__ float Bs[BK][PAD];
    const int s = blockIdx.z;
    const float* Bp = Bw + (size_t)s * K * DLLM;
    const float* bp = bias + (size_t)s * DLLM;
    const int tid = threadIdx.x;
    const int tx = tid & 15, ty = tid >> 4;
    const int nBase = blockIdx.x * BN;
    const int lr = tid >> 2, lc = (tid & 3) << 2;   // A loader
    const int br = tid >> 4, bc = (tid & 15) << 2;  // B loader
    float acc[4][4] = {};
    for (int k0 = 0; k0 < K; k0 += BK) {
        float4 a4 = *(const float4*)(A + (size_t)lr * K + k0 + lc);
        float4 b4 = *(const float4*)(Bp + (size_t)(k0 + br) * DLLM + nBase + bc);
        As[lc + 0][lr] = a4.x; As[lc + 1][lr] = a4.y;
        As[lc + 2][lr] = a4.z; As[lc + 3][lr] = a4.w;
        *(float4*)&Bs[br][bc] = b4;
        __syncthreads();
#pragma unroll
        for (int kk = 0; kk < BK; kk++) {
            float4 av = *(const float4*)&As[kk][ty << 2];
            float4 bv = *(const float4*)&Bs[kk][tx << 2];
            float am[4] = {av.x, av.y, av.z, av.w};
            float bm[4] = {bv.x, bv.y, bv.z, bv.w};
#pragma unroll
            for (int i = 0; i < 4; i++)
#pragma unroll
                for (int j = 0; j < 4; j++)
                    acc[i][j] += am[i] * bm[j];
        }
        __syncthreads();
    }
#pragma unroll
    for (int i = 0; i < 4; i++) {
        const int bidx = (ty << 2) + i;
#pragma unroll
        for (int j = 0; j < 4; j++) {
            const int n = nBase + (tx << 2) + j;
            outp[((size_t)bidx * 16 + slotBase + s) * DLLM + n] = acc[i][j] + bp[n];
        }
    }
}

// ---------------------------------------------------------------------------
// LayerNorm over each (b, slot) row of 4096.
// ---------------------------------------------------------------------------
__global__ void __launch_bounds__(256) ln_kernel(
    const float* __restrict__ x, const float* __restrict__ g,
    const float* __restrict__ be, float* __restrict__ out)
{
    __shared__ float rs[8], rss[8];
    __shared__ float s_mu, s_inv;
    const int row = blockIdx.x;
    const float4* xr = (const float4*)(x + (size_t)row * DLLM);
    const int tid = threadIdx.x, lane = tid & 31, warp = tid >> 5;
    float s = 0.f, ss = 0.f;
    for (int i = tid; i < DLLM / 4; i += 256) {
        float4 v = xr[i];
        s  += v.x + v.y + v.z + v.w;
        ss += v.x * v.x + v.y * v.y + v.z * v.z + v.w * v.w;
    }
#pragma unroll
    for (int off = 16; off; off >>= 1) {
        s  += __shfl_xor_sync(0xffffffffu, s, off);
        ss += __shfl_xor_sync(0xffffffffu, ss, off);
    }
    if (lane == 0) { rs[warp] = s; rss[warp] = ss; }
    __syncthreads();
    if (tid == 0) {
        float S = 0.f, SS = 0.f;
#pragma unroll
        for (int w = 0; w < 8; w++) { S += rs[w]; SS += rss[w]; }
        const float mu = S * (1.0f / DLLM);
        const float var = SS * (1.0f / DLLM) - mu * mu;
        s_mu = mu;
        s_inv = rsqrtf(var + 1e-5f);
    }
    __syncthreads();
    const float mu = s_mu, inv = s_inv;
    const float4* g4 = (const float4*)g;
    const float4* b4 = (const float4*)be;
    float4* outr = (float4*)(out + (size_t)row * DLLM);
    for (int i = tid; i < DLLM / 4; i += 256) {
        float4 v = xr[i], gv = g4[i], bv = b4[i];
        float4 r;
        r.x = (v.x - mu) * inv * gv.x + bv.x;
        r.y = (v.y - mu) * inv * gv.y + bv.y;
        r.z = (v.z - mu) * inv * gv.z + bv.z;
        r.w = (v.w - mu) * inv * gv.w + bv.w;
        outr[i] = r;
    }
}

// ---------------------------------------------------------------------------
// Host orchestration
// ---------------------------------------------------------------------------
extern "C" void kernel_launch(void* const* d_in, const int* in_sizes, int n_in,
                              void* d_out, int out_size)
{
    const float* hidden = (const float*)d_in[0];
    const float* fibers[3] = {(const float*)d_in[1], (const float*)d_in[2], (const float*)d_in[3]};
    const unsigned char* mask = (const unsigned char*)d_in[4];
    const float* Wq[3]    = {(const float*)d_in[5],  (const float*)d_in[7],  (const float*)d_in[9]};
    const float* bq[3]    = {(const float*)d_in[6],  (const float*)d_in[8],  (const float*)d_in[10]};
    const float* Wqkv[3]  = {(const float*)d_in[11], (const float*)d_in[15], (const float*)d_in[19]};
    const float* bqkv[3]  = {(const float*)d_in[12], (const float*)d_in[16], (const float*)d_in[20]};
    const float* Wo[3]    = {(const float*)d_in[13], (const float*)d_in[17], (const float*)d_in[21]};
    const float* bo[3]    = {(const float*)d_in[14], (const float*)d_in[18], (const float*)d_in[22]};
    const float* Wlift[3] = {(const float*)d_in[23], (const float*)d_in[25], (const float*)d_in[27]};
    const float* blift[3] = {(const float*)d_in[24], (const float*)d_in[26], (const float*)d_in[28]};
    const float* lng = (const float*)d_in[29];
    const float* lnb = (const float*)d_in[30];

    const int ds[3]       = {256, 512, 1024};
    const int nhs[3]      = {4, 8, 16};
    const int slots[3]    = {4, 8, 4};
    const int slotBase[3] = {0, 4, 12};

    float *qb, *qp, *kk, *vv, *oo, *o2, *part, *prefix;
    cudaGetSymbolAddress((void**)&qb, g_qb);
    cudaGetSymbolAddress((void**)&qp, g_qp);
    cudaGetSymbolAddress((void**)&kk, g_k);
    cudaGetSymbolAddress((void**)&vv, g_v);
    cudaGetSymbolAddress((void**)&oo, g_o);
    cudaGetSymbolAddress((void**)&o2, g_o2);
    cudaGetSymbolAddress((void**)&part, g_part);
    cudaGetSymbolAddress((void**)&prefix, g_prefix);

    for (int bi = 0; bi < 3; bi++) {
        const int d = ds[bi], nh = nhs[bi];
        const int MN = BATCH * d;
        const int rblocks = (MN + 255) / 256;

        // 1. bundle query: qb = hidden @ Wq^T + bq          (64, d)
        gemm_nt_splitk<<<dim3(d / 64, 1, 8), 256>>>(hidden, Wq[bi], part, d, DLLM);
        reduce8<<<rblocks, 256>>>(part, bq[bi], qb, MN, d, 1.0f);

        // 2. MHA q in-proj (+scale): qp = 0.125*(qb @ Wq_in^T + bq_in)
        gemm_nt_splitk<<<dim3(d / 64, 1, 8), 256>>>(qb, Wqkv[bi], part, d, d);
        reduce8<<<rblocks, 256>>>(part, bqkv[bi], qp, MN, d, 0.125f);

        // 3/4. K and V projections                          (2048, d)
        gemm_nt_full<<<dim3(d / 64, MEM / 64), 256>>>(
            fibers[bi], Wqkv[bi] + (size_t)d * d, bqkv[bi] + d, kk, d, d, 1.0f);
        gemm_nt_full<<<dim3(d / 64, MEM / 64), 256>>>(
            fibers[bi], Wqkv[bi] + (size_t)2 * d * d, bqkv[bi] + 2 * d, vv, d, d, 1.0f);

        // 5. attention
        attn_kernel<<<dim3(nh, BATCH), 256>>>(qp, kk, vv, mask, oo, d);

        // 6. out-proj: o2 = o @ Wo^T + bo
        gemm_nt_splitk<<<dim3(d / 64, 1, 8), 256>>>(oo, Wo[bi], part, d, d);
        reduce8<<<rblocks, 256>>>(part, bo[bi], o2, MN, d, 1.0f);

        // 7. lift into prefix slots
        gemm_nn_lift<<<dim3(DLLM / 64, 1, slots[bi]), 256>>>(
            o2, Wlift[bi], blift[bi], prefix, d, slotBase[bi]);
    }

    // 8. LayerNorm -> output
    ln_kernel<<<BATCH * 16, 256>>>(prefix, lng, lnb, (float*)d_out);
}

// round 3
// speedup vs baseline: 1.1398x; 1.1398x over previous
#include <cuda_runtime.h>
#include <cuda_bf16.h>
#include <cstdint>

// ---------------------------------------------------------------------------
// CrossBundleAttention — HMMA (mma.sync bf16 hi/lo) for KV-proj + lift,
// fp32 split-K for small GEMMs, fused batched attention, LayerNorm.
// B=64, M=2048, D_LLM=4096, bundles: (d=256,nh=4,s=4) (512,8,8) (1024,16,4)
// ---------------------------------------------------------------------------

#define BATCH 64
#define MEM   2048
#define DLLM  4096

// ======================= scratch (device globals) ==========================
__device__ float g_qb[BATCH * 1024];
__device__ float g_qp[BATCH * 1024];
__device__ float g_o [BATCH * 1024];
__device__ float g_o2[BATCH * 1024];
__device__ float g_part[8 * BATCH * 1024];
__device__ float g_kv[2 * MEM * 1024];               // K then V
__device__ float g_prefix[BATCH * 16 * DLLM];
__device__ __nv_bfloat16 g_fh[MEM * 1024],  g_fl[MEM * 1024];
__device__ __nv_bfloat16 g_wkvh[2 * 1024 * 1024], g_wkvl[2 * 1024 * 1024];
__device__ __nv_bfloat16 g_wlh[16777216], g_wll[16777216];   // transposed Wlift
__device__ __nv_bfloat16 g_o2h[128 * 1024], g_o2l[128 * 1024];

// ======================= conversion kernels ================================
__global__ void cvt_hilo(const float* __restrict__ src,
                         __nv_bfloat16* __restrict__ hi, __nv_bfloat16* __restrict__ lo, int n) {
    int i = blockIdx.x * 256 + threadIdx.x;
    if (i >= n) return;
    float x = src[i];
    __nv_bfloat16 h = __float2bfloat16(x);
    hi[i] = h;
    lo[i] = __float2bfloat16(x - __bfloat162float(h));
}

__global__ void cvt_hilo_pad(const float* __restrict__ src,
                             __nv_bfloat16* __restrict__ hi, __nv_bfloat16* __restrict__ lo,
                             int rows_valid, int Kd) {
    int i = blockIdx.x * 256 + threadIdx.x;
    if (i >= 128 * Kd) return;
    int r = i / Kd;
    if (r < rows_valid) {
        float x = src[i];
        __nv_bfloat16 h = __float2bfloat16(x);
        hi[i] = h;
        lo[i] = __float2bfloat16(x - __bfloat162float(h));
    } else {
        hi[i] = __float2bfloat16(0.f);
        lo[i] = __float2bfloat16(0.f);
    }
}

// Wlift (s, K, 4096) -> transposed hi/lo (s, 4096, K)
__global__ void transp_hilo(const float* __restrict__ src,
                            __nv_bfloat16* __restrict__ hi, __nv_bfloat16* __restrict__ lo, int K) {
    __shared__ float t[32][33];
    const int s = blockIdx.z;
    const int n0 = blockIdx.x * 32, k0 = blockIdx.y * 32;
    const int tx = threadIdx.x, ty = threadIdx.y;
    const float* sp = src + (size_t)s * K * DLLM;
#pragma unroll
    for (int j = 0; j < 32; j += 8)
        t[ty + j][tx] = sp[(size_t)(k0 + ty + j) * DLLM + n0 + tx];
    __syncthreads();
    size_t dbase = (size_t)s * DLLM * K;
#pragma unroll
    for (int j = 0; j < 32; j += 8) {
        float x = t[tx][ty + j];
        __nv_bfloat16 h = __float2bfloat16(x);
        size_t di = dbase + (size_t)(n0 + ty + j) * K + k0 + tx;
        hi[di] = h;
        lo[di] = __float2bfloat16(x - __bfloat162float(h));
    }
}

// ======================= HMMA hi/lo GEMM-NT ================================
// C[z][m][n] = sum_k A[m][k]*B[z][n][k] + bias[z][n]  (fp32 out, bf16 hi/lo in)
// Block tile 128x128, 8 warps of 64x32, K-chunk 64.
#define STR 72   // smem row stride in bf16 (64 data + 8 pad) -> conflict-free frags

__device__ __forceinline__ void mma16816(float* c, const uint32_t* a, const uint32_t* b) {
    asm volatile(
        "mma.sync.aligned.m16n8k16.row.col.f32.bf16.bf16.f32 "
        "{%0,%1,%2,%3}, {%4,%5,%6,%7}, {%8,%9}, {%0,%1,%2,%3};"
        : "+f"(c[0]), "+f"(c[1]), "+f"(c[2]), "+f"(c[3])
        : "r"(a[0]), "r"(a[1]), "r"(a[2]), "r"(a[3]), "r"(b[0]), "r"(b[1]));
}

#define HMMA_SMEM (4 * 128 * STR * 2)   // Ah, Al, Bh, Bl tiles = 73728 B

__global__ void __launch_bounds__(256) hmma_nt(
    const __nv_bfloat16* __restrict__ a_hi, const __nv_bfloat16* __restrict__ a_lo,
    const __nv_bfloat16* __restrict__ b_hi, const __nv_bfloat16* __restrict__ b_lo,
    const float* __restrict__ bias, long long bias_zstr,
    float* __restrict__ C, long long c_row, long long c_zstr,
    long long b_zstr, int K, int m_valid)
{
    extern __shared__ __nv_bfloat16 sm[];
    __nv_bfloat16* Ah = sm;
    __nv_bfloat16* Al = sm + 128 * STR;
    __nv_bfloat16* Bh = sm + 2 * 128 * STR;
    __nv_bfloat16* Bl = sm + 3 * 128 * STR;

    const int tid = threadIdx.x, wid = tid >> 5, lane = tid & 31;
    const int nBase = blockIdx.x << 7, mBase = blockIdx.y << 7, z = blockIdx.z;
    const int mW = (wid >> 2) << 6;      // warp M offset in tile (0/64)
    const int nW = (wid & 3) << 5;       // warp N offset in tile (0/32/64/96)
    const __nv_bfloat16* bh = b_hi + (size_t)z * b_zstr;
    const __nv_bfloat16* bl = b_lo + (size_t)z * b_zstr;

    float acc[4][4][4] = {};
    const int grp = lane >> 2;           // 0..7
    const int qid = lane & 3;            // 0..3

    for (int k0 = 0; k0 < K; k0 += 64) {
        // ---- stage tiles: 128 rows x 64 bf16 each (uint4 = 8 bf16) ----
#pragma unroll
        for (int it = 0; it < 4; it++) {
            const int i = (it << 8) + tid;
            const int r = i >> 3, c8 = (i & 7) << 3;
            const size_t ga = (size_t)(mBase + r) * K + k0 + c8;
            const size_t gb = (size_t)(nBase + r) * K + k0 + c8;
            const int so = r * STR + c8;
            *(uint4*)(Ah + so) = *(const uint4*)(a_hi + ga);
            *(uint4*)(Al + so) = *(const uint4*)(a_lo + ga);
            *(uint4*)(Bh + so) = *(const uint4*)(bh + gb);
            *(uint4*)(Bl + so) = *(const uint4*)(bl + gb);
        }
        __syncthreads();

#pragma unroll
        for (int kk = 0; kk < 4; kk++) {
            const int kc = (kk << 4) + (qid << 1);
            uint32_t ah[4][4], al[4][4], bhf[4][2], blf[4][2];
#pragma unroll
            for (int mi = 0; mi < 4; mi++) {
                const int r = mW + (mi << 4) + grp;
                ah[mi][0] = *(const uint32_t*)(Ah + r * STR + kc);
                ah[mi][1] = *(const uint32_t*)(Ah + (r + 8) * STR + kc);
                ah[mi][2] = *(const uint32_t*)(Ah + r * STR + kc + 8);
                ah[mi][3] = *(const uint32_t*)(Ah + (r + 8) * STR + kc + 8);
                al[mi][0] = *(const uint32_t*)(Al + r * STR + kc);
                al[mi][1] = *(const uint32_t*)(Al + (r + 8) * STR + kc);
                al[mi][2] = *(const uint32_t*)(Al + r * STR + kc + 8);
                al[mi][3] = *(const uint32_t*)(Al + (r + 8) * STR + kc + 8);
            }
#pragma unroll
            for (int ni = 0; ni < 4; ni++) {
                const int n = nW + (ni << 3) + grp;
                bhf[ni][0] = *(const uint32_t*)(Bh + n * STR + kc);
                bhf[ni][1] = *(const uint32_t*)(Bh + n * STR + kc + 8);
                blf[ni][0] = *(const uint32_t*)(Bl + n * STR + kc);
                blf[ni][1] = *(const uint32_t*)(Bl + n * STR + kc + 8);
            }
#pragma unroll
            for (int mi = 0; mi < 4; mi++)
#pragma unroll
                for (int ni = 0; ni < 4; ni++) {
                    mma16816(acc[mi][ni], ah[mi], bhf[ni]);
                    mma16816(acc[mi][ni], ah[mi], blf[ni]);
                    mma16816(acc[mi][ni], al[mi], bhf[ni]);
                }
        }
        __syncthreads();
    }

    // ---- epilogue ----
    const float* brow = bias + (size_t)z * bias_zstr;
    float* Cz = C + (size_t)z * c_zstr;
#pragma unroll
    for (int mi = 0; mi < 4; mi++) {
        const int r0 = mBase + mW + (mi << 4) + grp;
#pragma unroll
        for (int ni = 0; ni < 4; ni++) {
            const int c = nBase + nW + (ni << 3) + (qid << 1);
            if (r0 < m_valid) {
                float2 v = {acc[mi][ni][0] + brow[c], acc[mi][ni][1] + brow[c + 1]};
                *(float2*)(Cz + (size_t)r0 * c_row + c) = v;
            }
            if (r0 + 8 < m_valid) {
                float2 v = {acc[mi][ni][2] + brow[c], acc[mi][ni][3] + brow[c + 1]};
                *(float2*)(Cz + (size_t)(r0 + 8) * c_row + c) = v;
            }
        }
    }
}

// ======================= fp32 split-K GEMM (M=64) ==========================
#define BN 64
#define BK 16
#define PAD 68
__global__ void __launch_bounds__(256) gemm_nt_splitk(
    const float* __restrict__ A, const float* __restrict__ W,
    float* __restrict__ Cpart, int N, int K)
{
    __shared__ float As[BK][PAD];
    __shared__ float Ws[BK][PAD];
    const int tid = threadIdx.x;
    const int tx = tid & 15, ty = tid >> 4;
    const int nBase = blockIdx.x * BN;
    const int z = blockIdx.z;
    const int kc = K >> 3;
    const int lr = tid >> 2;
    const int lc = (tid & 3) << 2;
    const float* Ap = A + (size_t)lr * K + lc;
    const float* Wp = W + (size_t)(nBase + lr) * K + lc;
    float acc[4][4] = {};
    const int kEnd = z * kc + kc;
    for (int k0 = z * kc; k0 < kEnd; k0 += BK) {
        float4 a4 = *(const float4*)(Ap + k0);
        float4 w4 = *(const float4*)(Wp + k0);
        As[lc + 0][lr] = a4.x; As[lc + 1][lr] = a4.y;
        As[lc + 2][lr] = a4.z; As[lc + 3][lr] = a4.w;
        Ws[lc + 0][lr] = w4.x; Ws[lc + 1][lr] = w4.y;
        Ws[lc + 2][lr] = w4.z; Ws[lc + 3][lr] = w4.w;
        __syncthreads();
#pragma unroll
        for (int kk = 0; kk < BK; kk++) {
            float4 av = *(const float4*)&As[kk][ty << 2];
            float4 wv = *(const float4*)&Ws[kk][tx << 2];
            float am[4] = {av.x, av.y, av.z, av.w};
            float wm[4] = {wv.x, wv.y, wv.z, wv.w};
#pragma unroll
            for (int i = 0; i < 4; i++)
#pragma unroll
                for (int j = 0; j < 4; j++)
                    acc[i][j] += am[i] * wm[j];
        }
        __syncthreads();
    }
    float* Cp = Cpart + (size_t)z * BATCH * N;
#pragma unroll
    for (int i = 0; i < 4; i++) {
        const int m = (ty << 2) + i;
#pragma unroll
        for (int j = 0; j < 4; j++) {
            const int n = nBase + (tx << 2) + j;
            Cp[(size_t)m * N + n] = acc[i][j];
        }
    }
}

__global__ void reduce8(const float* __restrict__ part, const float* __restrict__ bias,
                        float* __restrict__ C, int MN, int N, float alpha)
{
    const int i = blockIdx.x * 256 + threadIdx.x;
    if (i >= MN) return;
    float s = bias[i % N];
#pragma unroll
    for (int z = 0; z < 8; z++) s += part[(size_t)z * MN + i];
    C[i] = alpha * s;
}

// ======================= batched-query attention ===========================
// grid (nh, B/8), block 256. 8 queries per block share K/V tile reads.
// dyn smem: qs[8*64] | sc[8*2048] | ts[64*65]  = 21056 floats
__global__ void __launch_bounds__(256) attn2(
    const float* __restrict__ qp, const float* __restrict__ Kp,
    const float* __restrict__ Vp, const unsigned char* __restrict__ mask,
    float* __restrict__ o, int d)
{
    extern __shared__ float smf[];
    float* qs = smf;                 // 512
    float* sc = smf + 512;           // 16384
    float* ts = smf + 512 + 16384;   // 64*65

    const int h = blockIdx.x, b0 = blockIdx.y << 3;
    const int base = h << 6;
    const int tid = threadIdx.x, lane = tid & 31, wid = tid >> 5;

    for (int i = tid; i < 512; i += 256) {
        int qq = i >> 6, k = i & 63;
        qs[i] = qp[(size_t)(b0 + qq) * d + base + k];
    }
    __syncthreads();

    const float4* qs4 = (const float4*)(qs + (wid << 6));
    const unsigned char* mrow = mask + (size_t)(b0 + wid) * MEM;

    // phase 1: scores
    for (int mc = 0; mc < MEM; mc += 64) {
        for (int i = tid; i < 64 * 64; i += 256) {
            int r = i >> 6, c = i & 63;
            ts[r * 65 + c] = Kp[(size_t)(mc + r) * d + base + c];
        }
        __syncthreads();
        float acc0 = 0.f, acc1 = 0.f;
        const float* t0 = ts + lane * 65;
        const float* t1 = ts + (lane + 32) * 65;
#pragma unroll
        for (int k4 = 0; k4 < 16; k4++) {
            float4 qv = qs4[k4];
            acc0 += qv.x * t0[k4 * 4] + qv.y * t0[k4 * 4 + 1] + qv.z * t0[k4 * 4 + 2] + qv.w * t0[k4 * 4 + 3];
            acc1 += qv.x * t1[k4 * 4] + qv.y * t1[k4 * 4 + 1] + qv.z * t1[k4 * 4 + 2] + qv.w * t1[k4 * 4 + 3];
        }
        sc[(wid << 11) + mc + lane]      = mrow[mc + lane]      ? -1e9f : acc0;
        sc[(wid << 11) + mc + 32 + lane] = mrow[mc + 32 + lane] ? -1e9f : acc1;
        __syncthreads();
    }

    // warp-local softmax (warp w owns query b0+w)
    float* row = sc + (wid << 11);
    float mx = -1e30f;
    for (int i = lane; i < MEM; i += 32) mx = fmaxf(mx, row[i]);
#pragma unroll
    for (int off = 16; off; off >>= 1) mx = fmaxf(mx, __shfl_xor_sync(0xffffffffu, mx, off));
    float sum = 0.f;
    for (int i = lane; i < MEM; i += 32) {
        float e = __expf(row[i] - mx);
        row[i] = e;
        sum += e;
    }
#pragma unroll
    for (int off = 16; off; off >>= 1) sum += __shfl_xor_sync(0xffffffffu, sum, off);
    const float inv = 1.f / sum;

    // phase 2: P @ V
    float acc0 = 0.f, acc1 = 0.f;
    for (int mc = 0; mc < MEM; mc += 64) {
        __syncthreads();
        for (int i = tid; i < 64 * 64; i += 256) {
            int r = i >> 6, c = i & 63;
            ts[r * 65 + c] = Vp[(size_t)(mc + r) * d + base + c];
        }
        __syncthreads();
        const float* pr = row + mc;
#pragma unroll 8
        for (int j = 0; j < 64; j++) {
            float p = pr[j];
            acc0 += p * ts[j * 65 + lane];
            acc1 += p * ts[j * 65 + lane + 32];
        }
    }
    o[(size_t)(b0 + wid) * d + base + lane]      = acc0 * inv;
    o[(size_t)(b0 + wid) * d + base + lane + 32] = acc1 * inv;
}

// ======================= LayerNorm =========================================
__global__ void __launch_bounds__(256) ln_kernel(
    const float* __restrict__ x, const float* __restrict__ g,
    const float* __restrict__ be, float* __restrict__ out)
{
    __shared__ float rs[8], rss[8];
    __shared__ float s_mu, s_inv;
    const int rowi = blockIdx.x;
    const float4* xr = (const float4*)(x + (size_t)rowi * DLLM);
    const int tid = threadIdx.x, lane = tid & 31, warp = tid >> 5;
    float s = 0.f, ss = 0.f;
    for (int i = tid; i < DLLM / 4; i += 256) {
        float4 v = xr[i];
        s  += v.x + v.y + v.z + v.w;
        ss += v.x * v.x + v.y * v.y + v.z * v.z + v.w * v.w;
    }
#pragma unroll
    for (int off = 16; off; off >>= 1) {
        s  += __shfl_xor_sync(0xffffffffu, s, off);
        ss += __shfl_xor_sync(0xffffffffu, ss, off);
    }
    if (lane == 0) { rs[warp] = s; rss[warp] = ss; }
    __syncthreads();
    if (tid == 0) {
        float S = 0.f, SS = 0.f;
#pragma unroll
        for (int w = 0; w < 8; w++) { S += rs[w]; SS += rss[w]; }
        const float mu = S * (1.0f / DLLM);
        const float var = SS * (1.0f / DLLM) - mu * mu;
        s_mu = mu;
        s_inv = rsqrtf(var + 1e-5f);
    }
    __syncthreads();
    const float mu = s_mu, inv = s_inv;
    const float4* g4 = (const float4*)g;
    const float4* b4 = (const float4*)be;
    float4* outr = (float4*)(out + (size_t)rowi * DLLM);
    for (int i = tid; i < DLLM / 4; i += 256) {
        float4 v = xr[i], gv = g4[i], bv = b4[i];
        float4 r;
        r.x = (v.x - mu) * inv * gv.x + bv.x;
        r.y = (v.y - mu) * inv * gv.y + bv.y;
        r.z = (v.z - mu) * inv * gv.z + bv.z;
        r.w = (v.w - mu) * inv * gv.w + bv.w;
        outr[i] = r;
    }
}

// ======================= host orchestration ================================
extern "C" void kernel_launch(void* const* d_in, const int* in_sizes, int n_in,
                              void* d_out, int out_size)
{
    const float* hidden = (const float*)d_in[0];
    const float* fibers[3] = {(const float*)d_in[1], (const float*)d_in[2], (const float*)d_in[3]};
    const unsigned char* mask = (const unsigned char*)d_in[4];
    const float* Wq[3]    = {(const float*)d_in[5],  (const float*)d_in[7],  (const float*)d_in[9]};
    const float* bq[3]    = {(const float*)d_in[6],  (const float*)d_in[8],  (const float*)d_in[10]};
    const float* Wqkv[3]  = {(const float*)d_in[11], (const float*)d_in[15], (const float*)d_in[19]};
    const float* bqkv[3]  = {(const float*)d_in[12], (const float*)d_in[16], (const float*)d_in[20]};
    const float* Wo[3]    = {(const float*)d_in[13], (const float*)d_in[17], (const float*)d_in[21]};
    const float* bo[3]    = {(const float*)d_in[14], (const float*)d_in[18], (const float*)d_in[22]};
    const float* Wlift[3] = {(const float*)d_in[23], (const float*)d_in[25], (const float*)d_in[27]};
    const float* blift[3] = {(const float*)d_in[24], (const float*)d_in[26], (const float*)d_in[28]};
    const float* lng = (const float*)d_in[29];
    const float* lnb = (const float*)d_in[30];

    const int ds[3]       = {256, 512, 1024};
    const int nhs[3]      = {4, 8, 16};
    const int slots[3]    = {4, 8, 4};
    const int slotBase[3] = {0, 4, 12};

    float *qb, *qp, *oo, *o2, *part, *kv, *prefix;
    __nv_bfloat16 *fh, *fl, *wkvh, *wkvl, *wlh, *wll, *o2h, *o2l;
    cudaGetSymbolAddress((void**)&qb, g_qb);
    cudaGetSymbolAddress((void**)&qp, g_qp);
    cudaGetSymbolAddress((void**)&oo, g_o);
    cudaGetSymbolAddress((void**)&o2, g_o2);
    cudaGetSymbolAddress((void**)&part, g_part);
    cudaGetSymbolAddress((void**)&kv, g_kv);
    cudaGetSymbolAddress((void**)&prefix, g_prefix);
    cudaGetSymbolAddress((void**)&fh, g_fh);
    cudaGetSymbolAddress((void**)&fl, g_fl);
    cudaGetSymbolAddress((void**)&wkvh, g_wkvh);
    cudaGetSymbolAddress((void**)&wkvl, g_wkvl);
    cudaGetSymbolAddress((void**)&wlh, g_wlh);
    cudaGetSymbolAddress((void**)&wll, g_wll);
    cudaGetSymbolAddress((void**)&o2h, g_o2h);
    cudaGetSymbolAddress((void**)&o2l, g_o2l);

    cudaFuncSetAttribute(hmma_nt, cudaFuncAttributeMaxDynamicSharedMemorySize, HMMA_SMEM);
    cudaFuncSetAttribute(attn2, cudaFuncAttributeMaxDynamicSharedMemorySize, 21056 * 4);

    for (int bi = 0; bi < 3; bi++) {
        const int d = ds[bi], nh = nhs[bi], s = slots[bi];
        const int MN = BATCH * d;
        const int rblocks = (MN + 255) / 256;

        // --- conversions ---
        cvt_hilo<<<(MEM * d + 255) / 256, 256>>>(fibers[bi], fh, fl, MEM * d);
        cvt_hilo<<<(2 * d * d + 255) / 256, 256>>>(Wqkv[bi] + (size_t)d * d, wkvh, wkvl, 2 * d * d);
        transp_hilo<<<dim3(DLLM / 32, d / 32, s), dim3(32, 8)>>>(Wlift[bi], wlh, wll, d);

        // --- q head + q in-proj (fp32 split-K) ---
        gemm_nt_splitk<<<dim3(d / 64, 1, 8), 256>>>(hidden, Wq[bi], part, d, DLLM);
        reduce8<<<rblocks, 256>>>(part, bq[bi], qb, MN, d, 1.0f);
        gemm_nt_splitk<<<dim3(d / 64, 1, 8), 256>>>(qb, Wqkv[bi], part, d, d);
        reduce8<<<rblocks, 256>>>(part, bqkv[bi], qp, MN, d, 0.125f);

        // --- K and V projections (HMMA hi/lo) ---
        hmma_nt<<<dim3(d / 128, MEM / 128, 2), 256, HMMA_SMEM>>>(
            fh, fl, wkvh, wkvl, bqkv[bi] + d, d,
            kv, d, (long long)MEM * d, (long long)d * d, d, MEM);

        // --- attention ---
        attn2<<<dim3(nh, BATCH / 8), 256, 21056 * 4>>>(
            qp, kv, kv + (size_t)MEM * d, mask, oo, d);

        // --- out-proj (fp32 split-K) ---
        gemm_nt_splitk<<<dim3(d / 64, 1, 8), 256>>>(oo, Wo[bi], part, d, d);
        reduce8<<<rblocks, 256>>>(part, bo[bi], o2, MN, d, 1.0f);

        // --- lift (HMMA hi/lo, M padded to 128) ---
        cvt_hilo_pad<<<(128 * d + 255) / 256, 256>>>(o2, o2h, o2l, BATCH, d);
        hmma_nt<<<dim3(DLLM / 128, 1, s), 256, HMMA_SMEM>>>(
            o2h, o2l, wlh, wll, blift[bi], DLLM,
            prefix + (size_t)slotBase[bi] * DLLM, 16 * DLLM, DLLM,
            (long long)DLLM * d, d, BATCH);
    }

    ln_kernel<<<BATCH * 16, 256>>>(prefix, lng, lnb, (float*)d_out);
}